// round 2
// baseline (speedup 1.0000x reference)
#include <cuda_runtime.h>
#include <cstdint>
#include <cstddef>

#define B_DIM 8
#define S_LEN 2048
#define D_EMB 512
#define H_NUM 8
#define D_HEAD 64
#define NTOK (B_DIM * S_LEN)          // 16384

// ---------------- scratch (static device globals; no runtime alloc) ----------
__device__ float g_q  [(size_t)NTOK * D_EMB];        // 32 MB
__device__ float g_kv [(size_t)NTOK * 2 * D_EMB];    // 64 MB
__device__ float g_att[(size_t)NTOK * D_EMB];        // 32 MB
__device__ float g_y  [(size_t)NTOK * D_EMB];        // 32 MB
__device__ float g_maskf[B_DIM * S_LEN];             // 64 KB

// ---------------- mask dtype detection + expansion ---------------------------
// mask logical shape (B,1,1,S) = 16384 elements; dtype could be u8 / i32 / f32
// / bf16 depending on harness conversion of jax bool. Inspect first 4096
// 32-bit words (16 KB — safe under every candidate dtype), classify, expand
// to float 0/1. Deterministic.
__global__ void mask_expand_kernel(const void* __restrict__ mraw,
                                   float* __restrict__ mf)
{
    const int tid = threadIdx.x;
    const unsigned int* w = (const unsigned int*)mraw;
    int lf_u8 = 0, lf_i32 = 0, lf_f32 = 0, lf_b16 = 0;
    for (int i = tid; i < 4096; i += 256) {
        unsigned int x = w[i];
        if (x == 0u) continue;
        if (x == 0x3F800000u) { lf_f32 = 1; continue; }          // fp32 1.0
        if (x == 0x00003F80u || x == 0x3F803F80u) { lf_b16 = 1; continue; }
        if (x == 1u) { lf_i32 = 1; continue; }
        bool u8ok = true;
        #pragma unroll
        for (int s = 0; s < 32; s += 8) {
            unsigned int byte = (x >> s) & 0xFFu;
            if (byte > 1u) u8ok = false;
        }
        if (u8ok) lf_u8 = 1;
    }
    int any_b16 = __syncthreads_or(lf_b16);
    int any_f32 = __syncthreads_or(lf_f32);
    int any_u8  = __syncthreads_or(lf_u8);
    int any_i32 = __syncthreads_or(lf_i32);

    int mode;                 // 0=u8, 1=i32, 2=f32, 3=bf16
    if (any_b16)      mode = 3;
    else if (any_f32) mode = 2;
    else if (any_u8)  mode = 0;   // u8 outranks i32: word==1 is ambiguous
    else if (any_i32) mode = 1;
    else              mode = 0;

    for (int j = tid; j < B_DIM * S_LEN; j += 256) {
        bool m;
        if (mode == 0)      m = ((const unsigned char*) mraw)[j] != 0;
        else if (mode == 1) m = ((const int*)           mraw)[j] != 0;
        else if (mode == 2) m = ((const float*)         mraw)[j] != 0.0f;
        else                m = ((const unsigned short*)mraw)[j] != 0;
        mf[j] = m ? 1.0f : 0.0f;
    }
}

// ---------------- fp32 SGEMM: C[M,N] = A[M,K] @ W[K,N] (+bias)(+residual) ----
// BM=128, BN=128, BK=16, 256 threads, 8x8 register micro-tiles.
__global__ __launch_bounds__(256)
void sgemm_kernel(const float* __restrict__ A, const float* __restrict__ W,
                  float* __restrict__ C, int M, int N, int K,
                  const float* __restrict__ bias,
                  const float* __restrict__ residual)
{
    __shared__ float As[16][132];   // stored transposed: As[k][m]
    __shared__ float Ws[16][132];   // Ws[k][n]

    const int tid = threadIdx.x;
    const int m0 = blockIdx.y * 128;
    const int n0 = blockIdx.x * 128;
    const int ty = tid >> 4, tx = tid & 15;

    float acc[8][8];
    #pragma unroll
    for (int i = 0; i < 8; i++)
        #pragma unroll
        for (int j = 0; j < 8; j++) acc[i][j] = 0.0f;

    const int alr = tid >> 2;           // 0..63
    const int alc = (tid & 3) << 2;     // 0,4,8,12
    const int wlr = tid >> 5;           // 0..7
    const int wlc = (tid & 31) << 2;    // 0..124

    for (int kb = 0; kb < K; kb += 16) {
        #pragma unroll
        for (int p = 0; p < 2; p++) {
            float4 a = *(const float4*)(A + (size_t)(m0 + alr + p * 64) * K + kb + alc);
            As[alc + 0][alr + p * 64] = a.x;
            As[alc + 1][alr + p * 64] = a.y;
            As[alc + 2][alr + p * 64] = a.z;
            As[alc + 3][alr + p * 64] = a.w;
            float4 wv = *(const float4*)(W + (size_t)(kb + wlr + p * 8) * N + n0 + wlc);
            *(float4*)&Ws[wlr + p * 8][wlc] = wv;
        }
        __syncthreads();
        #pragma unroll
        for (int kk = 0; kk < 16; kk++) {
            float af[8], wf[8];
            *(float4*)(af + 0) = *(const float4*)&As[kk][ty * 8 + 0];
            *(float4*)(af + 4) = *(const float4*)&As[kk][ty * 8 + 4];
            *(float4*)(wf + 0) = *(const float4*)&Ws[kk][tx * 8 + 0];
            *(float4*)(wf + 4) = *(const float4*)&Ws[kk][tx * 8 + 4];
            #pragma unroll
            for (int i = 0; i < 8; i++)
                #pragma unroll
                for (int j = 0; j < 8; j++)
                    acc[i][j] = fmaf(af[i], wf[j], acc[i][j]);
        }
        __syncthreads();
    }

    #pragma unroll
    for (int i = 0; i < 8; i++) {
        const int row = m0 + ty * 8 + i;
        #pragma unroll
        for (int j4 = 0; j4 < 8; j4 += 4) {
            const int col = n0 + tx * 8 + j4;
            float4 c = make_float4(acc[i][j4 + 0], acc[i][j4 + 1],
                                   acc[i][j4 + 2], acc[i][j4 + 3]);
            if (bias) {
                float4 bb = *(const float4*)(bias + col);
                c.x += bb.x; c.y += bb.y; c.z += bb.z; c.w += bb.w;
            }
            if (residual) {
                float4 r = *(const float4*)(residual + (size_t)row * N + col);
                c.x += r.x; c.y += r.y; c.z += r.z; c.w += r.w;
            }
            *(float4*)(C + (size_t)row * N + col) = c;
        }
    }
}

// ---------------- flash attention -------------------------------------------
// grid (S/64, H, B), 256 threads. 64x64 tiles, online softmax.
// smem: Qs/Ks transposed [d][i] stride 68, Vs [j][c] stride 68, Ss [i][j] stride 68.
#define TS 68
#define ATTN_SMEM (4 * 64 * TS * (int)sizeof(float))   // 69632 B

__global__ void attn_kernel(const float* __restrict__ bias,
                            const float* __restrict__ gamma_f)
{
    extern __shared__ float sm[];
    float* Qs = sm;
    float* Ks = sm + 64 * TS;
    float* Vs = sm + 2 * 64 * TS;
    float* Ss = sm + 3 * 64 * TS;

    const int tid = threadIdx.x;
    const int qt = blockIdx.x, h = blockIdx.y, b = blockIdx.z;
    const float g = gamma_f[h];
    const int nq0 = b * S_LEN + qt * 64;

    const int c4 = (tid & 15) << 2;     // 0..60
    const int r0 = tid >> 4;            // 0..15

    // load Q transposed, pre-scaled by 1/sqrt(64)=0.125 (exact)
    #pragma unroll
    for (int p = 0; p < 4; p++) {
        const int r = r0 + p * 16;
        float4 v = *(const float4*)(g_q + (size_t)(nq0 + r) * D_EMB + h * D_HEAD + c4);
        Qs[(c4 + 0) * TS + r] = v.x * 0.125f;
        Qs[(c4 + 1) * TS + r] = v.y * 0.125f;
        Qs[(c4 + 2) * TS + r] = v.z * 0.125f;
        Qs[(c4 + 3) * TS + r] = v.w * 0.125f;
    }

    float O[16];
    #pragma unroll
    for (int e = 0; e < 16; e++) O[e] = 0.0f;
    float mrun = -1e30f, lrun = 0.0f;

    const int ty = tid >> 4, tx = tid & 15;
    const int r = tid >> 2, sg = tid & 3;

    for (int kt = 0; kt < S_LEN / 64; kt++) {
        __syncthreads();   // prior PV done reading Vs/Ss
        // load K (transposed) and V (direct)
        #pragma unroll
        for (int p = 0; p < 4; p++) {
            const int rr = r0 + p * 16;
            const size_t nk = (size_t)(b * S_LEN + kt * 64 + rr);
            float4 kvv = *(const float4*)(g_kv + nk * (2 * D_EMB) + h * D_HEAD + c4);
            Ks[(c4 + 0) * TS + rr] = kvv.x;
            Ks[(c4 + 1) * TS + rr] = kvv.y;
            Ks[(c4 + 2) * TS + rr] = kvv.z;
            Ks[(c4 + 3) * TS + rr] = kvv.w;
            float4 vv = *(const float4*)(g_kv + nk * (2 * D_EMB) + D_EMB + h * D_HEAD + c4);
            *(float4*)&Vs[rr * TS + c4] = vv;
        }
        __syncthreads();   // K,V (and Q on iter 0) visible

        // S = Q K^T : 4x4 micro-tile per thread
        float sa[16];
        #pragma unroll
        for (int e = 0; e < 16; e++) sa[e] = 0.0f;
        #pragma unroll 16
        for (int d = 0; d < 64; d++) {
            float4 qa = *(const float4*)(Qs + d * TS + ty * 4);
            float4 ka = *(const float4*)(Ks + d * TS + tx * 4);
            sa[ 0] = fmaf(qa.x, ka.x, sa[ 0]);
            sa[ 1] = fmaf(qa.x, ka.y, sa[ 1]);
            sa[ 2] = fmaf(qa.x, ka.z, sa[ 2]);
            sa[ 3] = fmaf(qa.x, ka.w, sa[ 3]);
            sa[ 4] = fmaf(qa.y, ka.x, sa[ 4]);
            sa[ 5] = fmaf(qa.y, ka.y, sa[ 5]);
            sa[ 6] = fmaf(qa.y, ka.z, sa[ 6]);
            sa[ 7] = fmaf(qa.y, ka.w, sa[ 7]);
            sa[ 8] = fmaf(qa.z, ka.x, sa[ 8]);
            sa[ 9] = fmaf(qa.z, ka.y, sa[ 9]);
            sa[10] = fmaf(qa.z, ka.z, sa[10]);
            sa[11] = fmaf(qa.z, ka.w, sa[11]);
            sa[12] = fmaf(qa.w, ka.x, sa[12]);
            sa[13] = fmaf(qa.w, ka.y, sa[13]);
            sa[14] = fmaf(qa.w, ka.z, sa[14]);
            sa[15] = fmaf(qa.w, ka.w, sa[15]);
        }

        // apply gamma*bias and mask; stage to Ss
        {
            float4 mk = *(const float4*)(g_maskf + b * S_LEN + kt * 64 + tx * 4);
            #pragma unroll
            for (int a = 0; a < 4; a++) {
                const int qi = qt * 64 + ty * 4 + a;
                float4 bi = *(const float4*)(bias + ((size_t)b * S_LEN + qi) * S_LEN
                                             + kt * 64 + tx * 4);
                float4 o;
                o.x = (mk.x != 0.0f) ? -1e9f : fmaf(g, bi.x, sa[a * 4 + 0]);
                o.y = (mk.y != 0.0f) ? -1e9f : fmaf(g, bi.y, sa[a * 4 + 1]);
                o.z = (mk.z != 0.0f) ? -1e9f : fmaf(g, bi.z, sa[a * 4 + 2]);
                o.w = (mk.w != 0.0f) ? -1e9f : fmaf(g, bi.w, sa[a * 4 + 3]);
                *(float4*)&Ss[(ty * 4 + a) * TS + tx * 4] = o;
            }
        }
        // rows 8w..8w+7 of Ss are produced AND consumed entirely by warp w
        __syncwarp();

        // online softmax: 4 threads per row, 16 cols each
        {
            float vb[16];
            float* rp = Ss + r * TS + sg * 16;
            *(float4*)(vb +  0) = *(const float4*)(rp +  0);
            *(float4*)(vb +  4) = *(const float4*)(rp +  4);
            *(float4*)(vb +  8) = *(const float4*)(rp +  8);
            *(float4*)(vb + 12) = *(const float4*)(rp + 12);
            float tmax = vb[0];
            #pragma unroll
            for (int e = 1; e < 16; e++) tmax = fmaxf(tmax, vb[e]);
            tmax = fmaxf(tmax, __shfl_xor_sync(0xffffffffu, tmax, 1));
            tmax = fmaxf(tmax, __shfl_xor_sync(0xffffffffu, tmax, 2));
            const float mnew = fmaxf(mrun, tmax);
            const float corr = __expf(mrun - mnew);
            float ps = 0.0f;
            #pragma unroll
            for (int e = 0; e < 16; e++) { vb[e] = __expf(vb[e] - mnew); ps += vb[e]; }
            ps += __shfl_xor_sync(0xffffffffu, ps, 1);
            ps += __shfl_xor_sync(0xffffffffu, ps, 2);
            lrun = lrun * corr + ps;
            mrun = mnew;
            *(float4*)(rp +  0) = *(float4*)(vb +  0);
            *(float4*)(rp +  4) = *(float4*)(vb +  4);
            *(float4*)(rp +  8) = *(float4*)(vb +  8);
            *(float4*)(rp + 12) = *(float4*)(vb + 12);
            #pragma unroll
            for (int e = 0; e < 16; e++) O[e] *= corr;
        }
        __syncwarp();      // probs for row r complete (siblings in same warp)

        // O += P @ V  (thread owns row r, cols sg*16..sg*16+15)
        {
            const float* pr = Ss + r * TS;
            #pragma unroll 8
            for (int j = 0; j < 64; j++) {
                const float p = pr[j];
                const float* vp = Vs + j * TS + sg * 16;
                float4 v0 = *(const float4*)(vp + 0);
                float4 v1 = *(const float4*)(vp + 4);
                float4 v2 = *(const float4*)(vp + 8);
                float4 v3 = *(const float4*)(vp + 12);
                O[ 0] = fmaf(p, v0.x, O[ 0]);
                O[ 1] = fmaf(p, v0.y, O[ 1]);
                O[ 2] = fmaf(p, v0.z, O[ 2]);
                O[ 3] = fmaf(p, v0.w, O[ 3]);
                O[ 4] = fmaf(p, v1.x, O[ 4]);
                O[ 5] = fmaf(p, v1.y, O[ 5]);
                O[ 6] = fmaf(p, v1.z, O[ 6]);
                O[ 7] = fmaf(p, v1.w, O[ 7]);
                O[ 8] = fmaf(p, v2.x, O[ 8]);
                O[ 9] = fmaf(p, v2.y, O[ 9]);
                O[10] = fmaf(p, v2.z, O[10]);
                O[11] = fmaf(p, v2.w, O[11]);
                O[12] = fmaf(p, v3.x, O[12]);
                O[13] = fmaf(p, v3.y, O[13]);
                O[14] = fmaf(p, v3.z, O[14]);
                O[15] = fmaf(p, v3.w, O[15]);
            }
        }
    }

    const float inv = 1.0f / lrun;
    float* op = g_att + (size_t)(nq0 + r) * D_EMB + h * D_HEAD + sg * 16;
    *(float4*)(op +  0) = make_float4(O[ 0]*inv, O[ 1]*inv, O[ 2]*inv, O[ 3]*inv);
    *(float4*)(op +  4) = make_float4(O[ 4]*inv, O[ 5]*inv, O[ 6]*inv, O[ 7]*inv);
    *(float4*)(op +  8) = make_float4(O[ 8]*inv, O[ 9]*inv, O[10]*inv, O[11]*inv);
    *(float4*)(op + 12) = make_float4(O[12]*inv, O[13]*inv, O[14]*inv, O[15]*inv);
}

// ---------------- layernorm: one warp per row of 512 -------------------------
__global__ void ln_kernel(const float* __restrict__ y,
                          const float* __restrict__ lng,
                          const float* __restrict__ lnb,
                          float* __restrict__ out)
{
    const int warp = threadIdx.x >> 5, lane = threadIdx.x & 31;
    const int row = blockIdx.x * 8 + warp;
    const float* yr = y + (size_t)row * D_EMB;

    float v[16];
    #pragma unroll
    for (int c = 0; c < 4; c++)
        *(float4*)(v + c * 4) = *(const float4*)(yr + c * 128 + lane * 4);

    float s = 0.0f;
    #pragma unroll
    for (int e = 0; e < 16; e++) s += v[e];
    #pragma unroll
    for (int off = 16; off > 0; off >>= 1) s += __shfl_xor_sync(0xffffffffu, s, off);
    const float mu = s * (1.0f / 512.0f);

    float sq = 0.0f;
    #pragma unroll
    for (int e = 0; e < 16; e++) { const float d = v[e] - mu; sq = fmaf(d, d, sq); }
    #pragma unroll
    for (int off = 16; off > 0; off >>= 1) sq += __shfl_xor_sync(0xffffffffu, sq, off);
    const float rstd = rsqrtf(sq * (1.0f / 512.0f) + 1e-5f);

    #pragma unroll
    for (int c = 0; c < 4; c++) {
        const int col = c * 128 + lane * 4;
        float4 gg = *(const float4*)(lng + col);
        float4 bb = *(const float4*)(lnb + col);
        float4 o;
        o.x = (v[c*4+0] - mu) * rstd * gg.x + bb.x;
        o.y = (v[c*4+1] - mu) * rstd * gg.y + bb.y;
        o.z = (v[c*4+2] - mu) * rstd * gg.z + bb.z;
        o.w = (v[c*4+3] - mu) * rstd * gg.w + bb.w;
        *(float4*)(out + (size_t)row * D_EMB + col) = o;
    }
}

// ---------------- launch ------------------------------------------------------
extern "C" void kernel_launch(void* const* d_in, const int* in_sizes, int n_in,
                              void* d_out, int out_size)
{
    (void)in_sizes; (void)n_in; (void)out_size;
    const float* x_p     = (const float*)d_in[0];
    const float* x_pcre  = (const float*)d_in[1];
    const float* bias    = (const float*)d_in[2];
    const void*  mask    = d_in[3];
    const float* Wq      = (const float*)d_in[4];
    const float* Wkv     = (const float*)d_in[5];
    const float* Wff     = (const float*)d_in[6];
    const float* bff     = (const float*)d_in[7];
    const float* gamma_f = (const float*)d_in[8];
    const float* ln_g    = (const float*)d_in[9];
    const float* ln_b    = (const float*)d_in[10];
    float* out = (float*)d_out;

    float *gq, *gkv, *gatt, *gy, *gmf;
    cudaGetSymbolAddress((void**)&gq,  g_q);
    cudaGetSymbolAddress((void**)&gkv, g_kv);
    cudaGetSymbolAddress((void**)&gatt,g_att);
    cudaGetSymbolAddress((void**)&gy,  g_y);
    cudaGetSymbolAddress((void**)&gmf, g_maskf);

    cudaFuncSetAttribute(attn_kernel, cudaFuncAttributeMaxDynamicSharedMemorySize,
                         ATTN_SMEM);

    mask_expand_kernel<<<1, 256>>>(mask, gmf);
    sgemm_kernel<<<dim3( 4, 128), 256>>>(x_p,    Wq,  gq,  NTOK,  512, 512, nullptr, nullptr);
    sgemm_kernel<<<dim3( 8, 128), 256>>>(x_pcre, Wkv, gkv, NTOK, 1024, 512, nullptr, nullptr);
    attn_kernel<<<dim3(S_LEN / 64, H_NUM, B_DIM), 256, ATTN_SMEM>>>(bias, gamma_f);
    sgemm_kernel<<<dim3( 4, 128), 256>>>(gatt,   Wff, gy,  NTOK,  512, 512, bff, x_p);
    ln_kernel<<<NTOK / 8, 256>>>(gy, ln_g, ln_b, out);
}

// round 6
// speedup vs baseline: 2.1275x; 2.1275x over previous
#include <cuda_runtime.h>
#include <cstdint>
#include <cstddef>

#define B_DIM 8
#define S_LEN 2048
#define D_EMB 512
#define H_NUM 8
#define D_HEAD 64
#define NTOK (B_DIM * S_LEN)          // 16384

// ---------------- scratch (static device globals; no runtime alloc) ----------
__device__ float g_q  [(size_t)NTOK * D_EMB];        // 32 MB
__device__ float g_kv [(size_t)NTOK * 2 * D_EMB];    // 64 MB
__device__ float g_att[(size_t)NTOK * D_EMB];        // 32 MB
__device__ float g_y  [(size_t)NTOK * D_EMB];        // 32 MB
__device__ float g_maskf[B_DIM * S_LEN];             // 64 KB

// ---------------- mask dtype detection + expansion ---------------------------
__global__ void mask_expand_kernel(const void* __restrict__ mraw,
                                   float* __restrict__ mf)
{
    const int tid = threadIdx.x;
    const unsigned int* w = (const unsigned int*)mraw;
    int lf_u8 = 0, lf_i32 = 0, lf_f32 = 0, lf_b16 = 0;
    for (int i = tid; i < 4096; i += 256) {
        unsigned int x = w[i];
        if (x == 0u) continue;
        if (x == 0x3F800000u) { lf_f32 = 1; continue; }          // fp32 1.0
        if (x == 0x00003F80u || x == 0x3F803F80u) { lf_b16 = 1; continue; }
        if (x == 1u) { lf_i32 = 1; continue; }
        bool u8ok = true;
        #pragma unroll
        for (int s = 0; s < 32; s += 8) {
            unsigned int byte = (x >> s) & 0xFFu;
            if (byte > 1u) u8ok = false;
        }
        if (u8ok) lf_u8 = 1;
    }
    int any_b16 = __syncthreads_or(lf_b16);
    int any_f32 = __syncthreads_or(lf_f32);
    int any_u8  = __syncthreads_or(lf_u8);
    int any_i32 = __syncthreads_or(lf_i32);

    int mode;                 // 0=u8, 1=i32, 2=f32, 3=bf16
    if (any_b16)      mode = 3;
    else if (any_f32) mode = 2;
    else if (any_u8)  mode = 0;
    else if (any_i32) mode = 1;
    else              mode = 0;

    for (int j = tid; j < B_DIM * S_LEN; j += 256) {
        bool m;
        if (mode == 0)      m = ((const unsigned char*) mraw)[j] != 0;
        else if (mode == 1) m = ((const int*)           mraw)[j] != 0;
        else if (mode == 2) m = ((const float*)         mraw)[j] != 0.0f;
        else                m = ((const unsigned short*)mraw)[j] != 0;
        mf[j] = m ? 1.0f : 0.0f;
    }
}

// ---------------- fp32 SGEMM: C[M,N] = A[M,K] @ W[K,N] (+bias)(+residual) ----
__global__ __launch_bounds__(256)
void sgemm_kernel(const float* __restrict__ A, const float* __restrict__ W,
                  float* __restrict__ C, int M, int N, int K,
                  const float* __restrict__ bias,
                  const float* __restrict__ residual)
{
    __shared__ float As[16][132];   // As[k][m]
    __shared__ float Ws[16][132];   // Ws[k][n]

    const int tid = threadIdx.x;
    const int m0 = blockIdx.y * 128;
    const int n0 = blockIdx.x * 128;
    const int ty = tid >> 4, tx = tid & 15;

    float acc[8][8];
    #pragma unroll
    for (int i = 0; i < 8; i++)
        #pragma unroll
        for (int j = 0; j < 8; j++) acc[i][j] = 0.0f;

    const int alr = tid >> 2;
    const int alc = (tid & 3) << 2;
    const int wlr = tid >> 5;
    const int wlc = (tid & 31) << 2;

    for (int kb = 0; kb < K; kb += 16) {
        #pragma unroll
        for (int p = 0; p < 2; p++) {
            float4 a = *(const float4*)(A + (size_t)(m0 + alr + p * 64) * K + kb + alc);
            As[alc + 0][alr + p * 64] = a.x;
            As[alc + 1][alr + p * 64] = a.y;
            As[alc + 2][alr + p * 64] = a.z;
            As[alc + 3][alr + p * 64] = a.w;
            float4 wv = *(const float4*)(W + (size_t)(kb + wlr + p * 8) * N + n0 + wlc);
            *(float4*)&Ws[wlr + p * 8][wlc] = wv;
        }
        __syncthreads();
        #pragma unroll
        for (int kk = 0; kk < 16; kk++) {
            float af[8], wf[8];
            *(float4*)(af + 0) = *(const float4*)&As[kk][ty * 8 + 0];
            *(float4*)(af + 4) = *(const float4*)&As[kk][ty * 8 + 4];
            *(float4*)(wf + 0) = *(const float4*)&Ws[kk][tx * 8 + 0];
            *(float4*)(wf + 4) = *(const float4*)&Ws[kk][tx * 8 + 4];
            #pragma unroll
            for (int i = 0; i < 8; i++)
                #pragma unroll
                for (int j = 0; j < 8; j++)
                    acc[i][j] = fmaf(af[i], wf[j], acc[i][j]);
        }
        __syncthreads();
    }

    #pragma unroll
    for (int i = 0; i < 8; i++) {
        const int row = m0 + ty * 8 + i;
        #pragma unroll
        for (int j4 = 0; j4 < 8; j4 += 4) {
            const int col = n0 + tx * 8 + j4;
            float4 c = make_float4(acc[i][j4 + 0], acc[i][j4 + 1],
                                   acc[i][j4 + 2], acc[i][j4 + 3]);
            if (bias) {
                float4 bb = *(const float4*)(bias + col);
                c.x += bb.x; c.y += bb.y; c.z += bb.z; c.w += bb.w;
            }
            if (residual) {
                float4 r = *(const float4*)(residual + (size_t)row * N + col);
                c.x += r.x; c.y += r.y; c.z += r.z; c.w += r.w;
            }
            *(float4*)(C + (size_t)row * N + col) = c;
        }
    }
}

// ---------------- flash attention v2: 128q x 128k tiles ----------------------
// 256 threads as 16(ty) x 16(tx).
// QK^T: 8x8 micro-tile (rows ty*8.., cols tx*8..)   -> 1.0 FMA/byte of LDS
// PV:   8 rows x 4 cols per thread, j-chunks of 4   -> 0.67 FMA/byte
// softmax: 2 threads per row (128 rows), running m/l/corr in smem arrays.
#define TQ 128
#define TK 128
#define QSTR 132
#define VSTR 68
#define ATTN_SMEM ((2 * 64 * QSTR + TK * VSTR + TQ * QSTR + 3 * TQ) * (int)sizeof(float))

__global__ __launch_bounds__(256, 1)
void attn_kernel(const float* __restrict__ bias,
                 const float* __restrict__ gamma_f)
{
    extern __shared__ float sm[];
    float* Qs = sm;                        // [64][QSTR]  (transposed: [d][q])
    float* Ks = Qs + 64 * QSTR;            // [64][QSTR]  (transposed: [d][k])
    float* Vs = Ks + 64 * QSTR;            // [TK][VSTR]  ([k][c])
    float* Ss = Vs + TK * VSTR;            // [TQ][QSTR]  scores / probs
    float* m_s    = Ss + TQ * QSTR;        // [TQ]
    float* l_s    = m_s + TQ;              // [TQ]
    float* corr_s = l_s + TQ;              // [TQ]

    const int tid = threadIdx.x;
    const int qt = blockIdx.x, h = blockIdx.y, b = blockIdx.z;
    const float g = gamma_f[h];
    const int nq0 = b * S_LEN + qt * TQ;
    const int ty = tid >> 4, tx = tid & 15;
    const int c4 = tx << 2;                // dim offset 0..60

    // ---- load Q transposed, pre-scaled by 1/sqrt(64)=0.125 (exact) ----
    #pragma unroll
    for (int p = 0; p < 8; p++) {
        const int row = ty + p * 16;
        float4 v = *(const float4*)(g_q + (size_t)(nq0 + row) * D_EMB + h * D_HEAD + c4);
        Qs[(c4 + 0) * QSTR + row] = v.x * 0.125f;
        Qs[(c4 + 1) * QSTR + row] = v.y * 0.125f;
        Qs[(c4 + 2) * QSTR + row] = v.z * 0.125f;
        Qs[(c4 + 3) * QSTR + row] = v.w * 0.125f;
    }
    if (tid < TQ) { m_s[tid] = -1e30f; l_s[tid] = 0.0f; }

    float O[32];
    #pragma unroll
    for (int e = 0; e < 32; e++) O[e] = 0.0f;

    for (int kt = 0; kt < S_LEN / TK; kt++) {
        __syncthreads();    // previous PV done with Vs/Ss; Ks free
        // ---- load K (transposed) and V ----
        #pragma unroll
        for (int p = 0; p < 8; p++) {
            const int row = ty + p * 16;
            const size_t nk = (size_t)(b * S_LEN + kt * TK + row);
            float4 kv = *(const float4*)(g_kv + nk * (2 * D_EMB) + h * D_HEAD + c4);
            Ks[(c4 + 0) * QSTR + row] = kv.x;
            Ks[(c4 + 1) * QSTR + row] = kv.y;
            Ks[(c4 + 2) * QSTR + row] = kv.z;
            Ks[(c4 + 3) * QSTR + row] = kv.w;
            float4 vv = *(const float4*)(g_kv + nk * (2 * D_EMB) + D_EMB + h * D_HEAD + c4);
            *(float4*)(Vs + row * VSTR + c4) = vv;
        }
        __syncthreads();

        // ---- S = Q K^T : 8x8 micro-tile ----
        float acc[64];
        #pragma unroll
        for (int e = 0; e < 64; e++) acc[e] = 0.0f;
        #pragma unroll 4
        for (int d = 0; d < 64; d++) {
            float qf[8], kf[8];
            *(float4*)(qf + 0) = *(const float4*)(Qs + d * QSTR + ty * 8 + 0);
            *(float4*)(qf + 4) = *(const float4*)(Qs + d * QSTR + ty * 8 + 4);
            *(float4*)(kf + 0) = *(const float4*)(Ks + d * QSTR + tx * 8 + 0);
            *(float4*)(kf + 4) = *(const float4*)(Ks + d * QSTR + tx * 8 + 4);
            #pragma unroll
            for (int i = 0; i < 8; i++)
                #pragma unroll
                for (int j = 0; j < 8; j++)
                    acc[i * 8 + j] = fmaf(qf[i], kf[j], acc[i * 8 + j]);
        }

        // ---- gamma*bias + mask, stage raw scores to Ss ----
        {
            float mk[8];
            *(float4*)(mk + 0) = *(const float4*)(g_maskf + b * S_LEN + kt * TK + tx * 8 + 0);
            *(float4*)(mk + 4) = *(const float4*)(g_maskf + b * S_LEN + kt * TK + tx * 8 + 4);
            #pragma unroll
            for (int i = 0; i < 8; i++) {
                const int qi = qt * TQ + ty * 8 + i;
                const float* bp = bias + ((size_t)b * S_LEN + qi) * S_LEN + kt * TK + tx * 8;
                float4 b0 = *(const float4*)(bp + 0);
                float4 b1 = *(const float4*)(bp + 4);
                float4 o0, o1;
                o0.x = (mk[0] != 0.0f) ? -1e9f : fmaf(g, b0.x, acc[i * 8 + 0]);
                o0.y = (mk[1] != 0.0f) ? -1e9f : fmaf(g, b0.y, acc[i * 8 + 1]);
                o0.z = (mk[2] != 0.0f) ? -1e9f : fmaf(g, b0.z, acc[i * 8 + 2]);
                o0.w = (mk[3] != 0.0f) ? -1e9f : fmaf(g, b0.w, acc[i * 8 + 3]);
                o1.x = (mk[4] != 0.0f) ? -1e9f : fmaf(g, b1.x, acc[i * 8 + 4]);
                o1.y = (mk[5] != 0.0f) ? -1e9f : fmaf(g, b1.y, acc[i * 8 + 5]);
                o1.z = (mk[6] != 0.0f) ? -1e9f : fmaf(g, b1.z, acc[i * 8 + 6]);
                o1.w = (mk[7] != 0.0f) ? -1e9f : fmaf(g, b1.w, acc[i * 8 + 7]);
                *(float4*)(Ss + (ty * 8 + i) * QSTR + tx * 8 + 0) = o0;
                *(float4*)(Ss + (ty * 8 + i) * QSTR + tx * 8 + 4) = o1;
            }
        }
        __syncthreads();

        // ---- online softmax: 2 threads per row, 64 cols each ----
        {
            const int r = tid >> 1, hf = tid & 1;
            float* rp = Ss + r * QSTR + hf * 64;
            float tmax = -1e30f;
            #pragma unroll
            for (int k4 = 0; k4 < 64; k4 += 4) {
                float4 v = *(const float4*)(rp + k4);
                tmax = fmaxf(tmax, fmaxf(fmaxf(v.x, v.y), fmaxf(v.z, v.w)));
            }
            tmax = fmaxf(tmax, __shfl_xor_sync(0xffffffffu, tmax, 1));
            const float mold = m_s[r];
            const float mnew = fmaxf(mold, tmax);
            const float corr = __expf(mold - mnew);
            float ps = 0.0f;
            #pragma unroll
            for (int k4 = 0; k4 < 64; k4 += 4) {
                float4 v = *(const float4*)(rp + k4);
                v.x = __expf(v.x - mnew);
                v.y = __expf(v.y - mnew);
                v.z = __expf(v.z - mnew);
                v.w = __expf(v.w - mnew);
                ps += v.x + v.y + v.z + v.w;
                *(float4*)(rp + k4) = v;
            }
            ps += __shfl_xor_sync(0xffffffffu, ps, 1);
            if (hf == 0) {
                m_s[r] = mnew;
                l_s[r] = l_s[r] * corr + ps;
                corr_s[r] = corr;
            }
        }
        __syncthreads();

        // ---- rescale O, then O += P @ V ----
        #pragma unroll
        for (int i = 0; i < 8; i++) {
            const float c = corr_s[ty * 8 + i];
            O[i * 4 + 0] *= c; O[i * 4 + 1] *= c;
            O[i * 4 + 2] *= c; O[i * 4 + 3] *= c;
        }
        #pragma unroll 2
        for (int j = 0; j < TK; j += 4) {
            float4 v0 = *(const float4*)(Vs + (j + 0) * VSTR + tx * 4);
            float4 v1 = *(const float4*)(Vs + (j + 1) * VSTR + tx * 4);
            float4 v2 = *(const float4*)(Vs + (j + 2) * VSTR + tx * 4);
            float4 v3 = *(const float4*)(Vs + (j + 3) * VSTR + tx * 4);
            #pragma unroll
            for (int i = 0; i < 8; i++) {
                float4 pp = *(const float4*)(Ss + (ty * 8 + i) * QSTR + j);
                float a0 = O[i * 4 + 0], a1 = O[i * 4 + 1];
                float a2 = O[i * 4 + 2], a3 = O[i * 4 + 3];
                a0 = fmaf(pp.x, v0.x, a0); a1 = fmaf(pp.x, v0.y, a1);
                a2 = fmaf(pp.x, v0.z, a2); a3 = fmaf(pp.x, v0.w, a3);
                a0 = fmaf(pp.y, v1.x, a0); a1 = fmaf(pp.y, v1.y, a1);
                a2 = fmaf(pp.y, v1.z, a2); a3 = fmaf(pp.y, v1.w, a3);
                a0 = fmaf(pp.z, v2.x, a0); a1 = fmaf(pp.z, v2.y, a1);
                a2 = fmaf(pp.z, v2.z, a2); a3 = fmaf(pp.z, v2.w, a3);
                a0 = fmaf(pp.w, v3.x, a0); a1 = fmaf(pp.w, v3.y, a1);
                a2 = fmaf(pp.w, v3.z, a2); a3 = fmaf(pp.w, v3.w, a3);
                O[i * 4 + 0] = a0; O[i * 4 + 1] = a1;
                O[i * 4 + 2] = a2; O[i * 4 + 3] = a3;
            }
        }
    }

    // ---- epilogue: normalize and store ----
    #pragma unroll
    for (int i = 0; i < 8; i++) {
        const int row = ty * 8 + i;
        const float inv = 1.0f / l_s[row];
        float4 o = make_float4(O[i * 4 + 0] * inv, O[i * 4 + 1] * inv,
                               O[i * 4 + 2] * inv, O[i * 4 + 3] * inv);
        *(float4*)(g_att + (size_t)(nq0 + row) * D_EMB + h * D_HEAD + tx * 4) = o;
    }
}

// ---------------- layernorm: one warp per row of 512 -------------------------
__global__ void ln_kernel(const float* __restrict__ y,
                          const float* __restrict__ lng,
                          const float* __restrict__ lnb,
                          float* __restrict__ out)
{
    const int warp = threadIdx.x >> 5, lane = threadIdx.x & 31;
    const int row = blockIdx.x * 8 + warp;
    const float* yr = y + (size_t)row * D_EMB;

    float v[16];
    #pragma unroll
    for (int c = 0; c < 4; c++)
        *(float4*)(v + c * 4) = *(const float4*)(yr + c * 128 + lane * 4);

    float s = 0.0f;
    #pragma unroll
    for (int e = 0; e < 16; e++) s += v[e];
    #pragma unroll
    for (int off = 16; off > 0; off >>= 1) s += __shfl_xor_sync(0xffffffffu, s, off);
    const float mu = s * (1.0f / 512.0f);

    float sq = 0.0f;
    #pragma unroll
    for (int e = 0; e < 16; e++) { const float d = v[e] - mu; sq = fmaf(d, d, sq); }
    #pragma unroll
    for (int off = 16; off > 0; off >>= 1) sq += __shfl_xor_sync(0xffffffffu, sq, off);
    const float rstd = rsqrtf(sq * (1.0f / 512.0f) + 1e-5f);

    #pragma unroll
    for (int c = 0; c < 4; c++) {
        const int col = c * 128 + lane * 4;
        float4 gg = *(const float4*)(lng + col);
        float4 bb = *(const float4*)(lnb + col);
        float4 o;
        o.x = (v[c*4+0] - mu) * rstd * gg.x + bb.x;
        o.y = (v[c*4+1] - mu) * rstd * gg.y + bb.y;
        o.z = (v[c*4+2] - mu) * rstd * gg.z + bb.z;
        o.w = (v[c*4+3] - mu) * rstd * gg.w + bb.w;
        *(float4*)(out + (size_t)row * D_EMB + col) = o;
    }
}

// ---------------- launch ------------------------------------------------------
extern "C" void kernel_launch(void* const* d_in, const int* in_sizes, int n_in,
                              void* d_out, int out_size)
{
    (void)in_sizes; (void)n_in; (void)out_size;
    const float* x_p     = (const float*)d_in[0];
    const float* x_pcre  = (const float*)d_in[1];
    const float* bias    = (const float*)d_in[2];
    const void*  mask    = d_in[3];
    const float* Wq      = (const float*)d_in[4];
    const float* Wkv     = (const float*)d_in[5];
    const float* Wff     = (const float*)d_in[6];
    const float* bff     = (const float*)d_in[7];
    const float* gamma_f = (const float*)d_in[8];
    const float* ln_g    = (const float*)d_in[9];
    const float* ln_b    = (const float*)d_in[10];
    float* out = (float*)d_out;

    float *gq, *gkv, *gatt, *gy, *gmf;
    cudaGetSymbolAddress((void**)&gq,  g_q);
    cudaGetSymbolAddress((void**)&gkv, g_kv);
    cudaGetSymbolAddress((void**)&gatt,g_att);
    cudaGetSymbolAddress((void**)&gy,  g_y);
    cudaGetSymbolAddress((void**)&gmf, g_maskf);

    cudaFuncSetAttribute(attn_kernel, cudaFuncAttributeMaxDynamicSharedMemorySize,
                         ATTN_SMEM);

    mask_expand_kernel<<<1, 256>>>(mask, gmf);
    sgemm_kernel<<<dim3( 4, 128), 256>>>(x_p,    Wq,  gq,  NTOK,  512, 512, nullptr, nullptr);
    sgemm_kernel<<<dim3( 8, 128), 256>>>(x_pcre, Wkv, gkv, NTOK, 1024, 512, nullptr, nullptr);
    attn_kernel<<<dim3(S_LEN / TQ, H_NUM, B_DIM), 256, ATTN_SMEM>>>(bias, gamma_f);
    sgemm_kernel<<<dim3( 4, 128), 256>>>(gatt,   Wff, gy,  NTOK,  512, 512, bff, x_p);
    ln_kernel<<<NTOK / 8, 256>>>(gy, ln_g, ln_b, out);
}